// round 16
// baseline (speedup 1.0000x reference)
#include <cuda_runtime.h>
#include <cuda_fp16.h>
#include <cstdint>

// ---------------------------------------------------------------------------
// x[8,1024,1024] -> qkv proj -> 16-head attention -> out proj (+bias)
// Legacy mma.sync m16n8k16 fp16/fp32. GEMMs: CTA 128x128, 256 threads,
// 8 warps (4Mx2N, warp tile 32x64), 3-stage cp.async, 2 CTAs per SM
// (round-15 evidence: single fat CTA serializes on its own barriers).
// ---------------------------------------------------------------------------

constexpr int kDim   = 1024;
constexpr int kBatch = 8;
constexpr int kSeq   = 1024;
constexpr int kHeads = 16;
constexpr int kHd    = 64;

// fp16 scratch (allocation-free rule: __device__ globals)
__device__ __half g_xh    [kBatch * kSeq * kDim];
__device__ __half g_wqkvh [3 * kDim * kDim];
__device__ __half g_wprojh[kDim * kDim];
__device__ __half g_q[kBatch * kHeads * kSeq * kHd];   // pre-scaled by 0.125
__device__ __half g_k[kBatch * kHeads * kSeq * kHd];
__device__ __half g_v[kBatch * kHeads * kSeq * kHd];
__device__ __half g_att[kBatch * kSeq * kDim];

// ------------------------------ helpers ------------------------------------
__device__ __forceinline__ uint32_t smem_u32(const void* p) {
    uint32_t a;
    asm("{ .reg .u64 t; cvta.to.shared.u64 t, %1; cvt.u32.u64 %0, t; }"
        : "=r"(a) : "l"(p));
    return a;
}
__device__ __forceinline__ void mma_fp16(float* c, const unsigned* a, const unsigned* b) {
    asm volatile(
        "mma.sync.aligned.m16n8k16.row.col.f32.f16.f16.f32 "
        "{%0,%1,%2,%3}, {%4,%5,%6,%7}, {%8,%9}, {%0,%1,%2,%3};"
        : "+f"(c[0]), "+f"(c[1]), "+f"(c[2]), "+f"(c[3])
        : "r"(a[0]), "r"(a[1]), "r"(a[2]), "r"(a[3]), "r"(b[0]), "r"(b[1]));
}
__device__ __forceinline__ void ldm_x4(unsigned& r0, unsigned& r1, unsigned& r2,
                                       unsigned& r3, uint32_t addr) {
    asm volatile("ldmatrix.sync.aligned.m8n8.x4.shared.b16 {%0,%1,%2,%3}, [%4];"
                 : "=r"(r0), "=r"(r1), "=r"(r2), "=r"(r3) : "r"(addr));
}
__device__ __forceinline__ void ldm_x4_t(unsigned& r0, unsigned& r1, unsigned& r2,
                                         unsigned& r3, uint32_t addr) {
    asm volatile("ldmatrix.sync.aligned.m8n8.x4.trans.shared.b16 {%0,%1,%2,%3}, [%4];"
                 : "=r"(r0), "=r"(r1), "=r"(r2), "=r"(r3) : "r"(addr));
}
__device__ __forceinline__ void cp16(uint32_t dst, const void* src) {
    asm volatile("cp.async.cg.shared.global [%0], [%1], 16;" :: "r"(dst), "l"(src));
}
__device__ __forceinline__ void cp_commit() {
    asm volatile("cp.async.commit_group;" ::: "memory");
}
template <int N>
__device__ __forceinline__ void cp_wait() {
    asm volatile("cp.async.wait_group %0;" :: "n"(N) : "memory");
}
__device__ __forceinline__ unsigned h2u(float a, float b) {
    __half2 h = __floats2half2_rn(a, b);
    return *reinterpret_cast<unsigned*>(&h);
}
__device__ __forceinline__ float qredmax(float v) {
    v = fmaxf(v, __shfl_xor_sync(0xffffffffu, v, 1));
    v = fmaxf(v, __shfl_xor_sync(0xffffffffu, v, 2));
    return v;
}
__device__ __forceinline__ float qredsum(float v) {
    v += __shfl_xor_sync(0xffffffffu, v, 1);
    v += __shfl_xor_sync(0xffffffffu, v, 2);
    return v;
}

// ---------------------------------------------------------------------------
// fp32 -> fp16 conversion (which: 0=x, 1=w_qkv, 2=w_proj)
// ---------------------------------------------------------------------------
__global__ void cvt_kernel(const float* __restrict__ src, int which, int n4) {
    int i = blockIdx.x * blockDim.x + threadIdx.x;
    if (i >= n4) return;
    __half* dst = (which == 0) ? g_xh : (which == 1) ? g_wqkvh : g_wprojh;
    float4 v = ((const float4*)src)[i];
    uint2 u;
    u.x = h2u(v.x, v.y);
    u.y = h2u(v.z, v.w);
    ((uint2*)dst)[i] = u;
}

// ---------------------------------------------------------------------------
// GEMM: C[m, f] = sum_c A[m, c] * B[f, c]   (fp16 K-major both; mma row.col)
// CTA 128(M) x 128(N), 256 threads, 8 warps: wm=warp&3 (32-row group),
// wn=warp>>2 (64-col group). Warp tile 32x64. K-slab 64, 3-stage cp.async,
// 2 CTAs per SM (launch_bounds(256,2); smem 110592 x 2 = 221KB <= 228KB).
// Rows padded to 144B: ldmatrix 8-row phases hit 32 distinct banks.
// MODE 0: A=g_xh, B=g_wqkvh; scatter half to g_q (x0.125)/g_k/g_v
// MODE 1: A=g_att, B=g_wprojh; add bias, f32 out
// ---------------------------------------------------------------------------
constexpr uint32_t G_ROWB = 144;
constexpr uint32_t A_ST   = 128 * G_ROWB;            // 18432
constexpr uint32_t B_ST   = 128 * G_ROWB;            // 18432
constexpr uint32_t G_ST   = A_ST + B_ST;             // 36864 per stage
constexpr uint32_t SMEM_G = 3 * G_ST;                // 110592
constexpr int kSlabs = kDim / 64;                    // 16

template <int MODE>
__global__ __launch_bounds__(256, 2)
void gemm5(const float* __restrict__ bias, float* __restrict__ C) {
    extern __shared__ char sm[];
    const uint32_t sb = smem_u32(sm);
    const int tid = threadIdx.x, warp = tid >> 5, lane = tid & 31;
    const int wm = warp & 3, wn = warp >> 2;         // 4(M) x 2(N) warps
    const int tg = lane >> 2, tl = lane & 3;
    const int m0 = blockIdx.y * 128, n0 = blockIdx.x * 128;

    const __half* Ag = (MODE == 0) ? g_xh : g_att;
    const __half* Bg = (MODE == 0) ? g_wqkvh : g_wprojh;

    // Loaders: 128 rows each, 2 thr/row, 4 cp16 (64B half-row) per thread.
    const int lR = tid >> 1, lH = tid & 1;
    const __half* aG = Ag + (size_t)(m0 + lR) * kDim + lH * 32;
    const __half* bG = Bg + (size_t)(n0 + lR) * kDim + lH * 32;
    const uint32_t aD = sb + lR * G_ROWB + lH * 64;
    const uint32_t bD = sb + A_ST + lR * G_ROWB + lH * 64;

    float acc[2][8][4];
#pragma unroll
    for (int mt = 0; mt < 2; mt++)
#pragma unroll
        for (int nt = 0; nt < 8; nt++)
#pragma unroll
            for (int i = 0; i < 4; i++) acc[mt][nt][i] = 0.f;

    const uint32_t lOff = (lane & 15) * G_ROWB + (lane >> 4) * 16;

    // prologue: slabs 0 and 1
#pragma unroll
    for (int p = 0; p < 2; p++) {
        const uint32_t off = p * G_ST;
        const int k0 = p * 64;
#pragma unroll
        for (int c = 0; c < 4; c++) cp16(aD + off + c * 16, aG + k0 + c * 8);
#pragma unroll
        for (int c = 0; c < 4; c++) cp16(bD + off + c * 16, bG + k0 + c * 8);
        cp_commit();
    }

    for (int s = 0; s < kSlabs; s++) {
        if (s + 2 < kSlabs) {
            const uint32_t off = ((s + 2) % 3) * G_ST;
            const int k0 = (s + 2) * 64;
#pragma unroll
            for (int c = 0; c < 4; c++) cp16(aD + off + c * 16, aG + k0 + c * 8);
#pragma unroll
            for (int c = 0; c < 4; c++) cp16(bD + off + c * 16, bG + k0 + c * 8);
            cp_commit();
            cp_wait<2>();
        } else if (s + 1 < kSlabs) {
            cp_wait<1>();
        } else {
            cp_wait<0>();
        }
        __syncthreads();   // stage s ready, prior consumers done

        const uint32_t st = sb + (s % 3) * G_ST;
        const uint32_t aS = st + wm * 32 * G_ROWB + lOff;
        const uint32_t bS = st + A_ST + wn * 64 * G_ROWB + lOff;
#pragma unroll
        for (int ks = 0; ks < 4; ks++) {
            unsigned af[2][4], bf[8][2];
#pragma unroll
            for (int mt = 0; mt < 2; mt++)
                ldm_x4(af[mt][0], af[mt][1], af[mt][2], af[mt][3],
                       aS + mt * 16 * G_ROWB + ks * 32);
#pragma unroll
            for (int np = 0; np < 4; np++) {
                unsigned r0, r1, r2, r3;
                ldm_x4(r0, r1, r2, r3, bS + np * 16 * G_ROWB + ks * 32);
                bf[2 * np][0] = r0; bf[2 * np + 1][0] = r1;
                bf[2 * np][1] = r2; bf[2 * np + 1][1] = r3;
            }
#pragma unroll
            for (int mt = 0; mt < 2; mt++)
#pragma unroll
                for (int nt = 0; nt < 8; nt++)
                    mma_fp16(acc[mt][nt], af[mt], bf[nt]);
        }
        __syncthreads();   // all warps done with stage s before it is refilled
    }

    // Epilogue
#pragma unroll
    for (int mt = 0; mt < 2; mt++) {
        const int mLo = m0 + wm * 32 + mt * 16 + tg;
        const int mHi = mLo + 8;
#pragma unroll
        for (int nt = 0; nt < 8; nt++) {
            const int f = n0 + wn * 64 + nt * 8 + 2 * tl;
            if (MODE == 0) {
                const int which = f >> 10;
                const int hh    = (f >> 6) & 15;
                const int dd    = f & 63;
                const float sc  = (which == 0) ? 0.125f : 1.f;   // fold q scale
                __half* dst = (which == 0) ? g_q : ((which == 1) ? g_k : g_v);
                {
                    int bb = mLo >> 10, nn = mLo & 1023;
                    size_t idx = ((size_t)(bb * kHeads + hh) * kSeq + nn) * kHd + dd;
                    *(__half2*)(dst + idx) =
                        __floats2half2_rn(acc[mt][nt][0] * sc, acc[mt][nt][1] * sc);
                }
                {
                    int bb = mHi >> 10, nn = mHi & 1023;
                    size_t idx = ((size_t)(bb * kHeads + hh) * kSeq + nn) * kHd + dd;
                    *(__half2*)(dst + idx) =
                        __floats2half2_rn(acc[mt][nt][2] * sc, acc[mt][nt][3] * sc);
                }
            } else {
                const float b0v = bias[f], b1v = bias[f + 1];
                *(float2*)(C + (size_t)mLo * kDim + f) =
                    make_float2(acc[mt][nt][0] + b0v, acc[mt][nt][1] + b1v);
                *(float2*)(C + (size_t)mHi * kDim + f) =
                    make_float2(acc[mt][nt][2] + b0v, acc[mt][nt][3] + b1v);
            }
        }
    }
}

// ---------------------------------------------------------------------------
// Flash attention: CTA = 128 q-rows of one (b,h); 4 warps x 32 rows.
// KV tiles 64, cp.async double-buffered. K frags via ldmatrix; V frags via
// ldmatrix.trans on natural [kv][d] layout; P kept in registers. Q pre-scaled.
// ---------------------------------------------------------------------------
constexpr uint32_t A_KV   = 128 * G_ROWB;            // Q region size: 18432
constexpr uint32_t A_TILE = 64 * G_ROWB;             // 9216
constexpr uint32_t SMEM_A = A_KV + 2 * 2 * A_TILE;   // 55296

__global__ __launch_bounds__(128)
void attn2() {
    extern __shared__ char sm[];
    const uint32_t sQ = smem_u32(sm);
    const int bx = blockIdx.x;
    const int qt = bx & 7;
    const int bh = bx >> 3;
    const int bb = bh >> 4;
    const int hh = bh & 15;
    const int tid = threadIdx.x, warp = tid >> 5, lane = tid & 31;
    const int tg = lane >> 2, tl = lane & 3;
    const int q0 = qt * 128;
    const int wq = warp * 32;

    const __half* Qp = g_q + (size_t)(bb * kHeads + hh) * kSeq * kHd;
    const __half* Kp = g_k + (size_t)(bb * kHeads + hh) * kSeq * kHd;
    const __half* Vp = g_v + (size_t)(bb * kHeads + hh) * kSeq * kHd;

    const int kvRow = tid >> 1, kvHalf = tid & 1;

    // prologue: KV tile 0
    {
        const __half* ks = Kp + (size_t)kvRow * kHd + kvHalf * 32;
        const __half* vs = Vp + (size_t)kvRow * kHd + kvHalf * 32;
        const uint32_t dK = sQ + A_KV + kvRow * G_ROWB + kvHalf * 64;
        const uint32_t dV = dK + A_TILE;
#pragma unroll
        for (int j = 0; j < 4; j++) cp16(dK + j * 16, ks + j * 8);
#pragma unroll
        for (int j = 0; j < 4; j++) cp16(dV + j * 16, vs + j * 8);
        cp_commit();
    }

    // Stage Q (pre-scaled by 0.125 at QKV epilogue)
    {
        const __half* qr = Qp + (size_t)(q0 + tid) * kHd;
        char* qd = sm + tid * G_ROWB;
#pragma unroll
        for (int j = 0; j < 8; j++)
            *(uint4*)(qd + j * 16) = *(const uint4*)(qr + j * 8);
    }
    __syncthreads();

    const uint32_t lOff = (lane & 15) * G_ROWB + (lane >> 4) * 16;
    unsigned qf[4][2][4];
    {
        const uint32_t qBase = sQ + wq * G_ROWB + lOff;
#pragma unroll
        for (int ks = 0; ks < 4; ks++)
#pragma unroll
            for (int mt = 0; mt < 2; mt++)
                ldm_x4(qf[ks][mt][0], qf[ks][mt][1], qf[ks][mt][2], qf[ks][mt][3],
                       qBase + mt * 16 * G_ROWB + ks * 32);
    }

    float o[2][8][4];
#pragma unroll
    for (int mt = 0; mt < 2; mt++)
#pragma unroll
        for (int nt = 0; nt < 8; nt++)
#pragma unroll
            for (int i = 0; i < 4; i++) o[mt][nt][i] = 0.f;
    float mrun[2][2] = {{-1e30f, -1e30f}, {-1e30f, -1e30f}};
    float lrun[2][2] = {{0.f, 0.f}, {0.f, 0.f}};

    for (int t = 0; t < 16; t++) {
        if (t + 1 < 16) {
            const uint32_t base = sQ + A_KV + ((t + 1) & 1) * 2 * A_TILE;
            const __half* ks = Kp + (size_t)((t + 1) * 64 + kvRow) * kHd + kvHalf * 32;
            const __half* vs = Vp + (size_t)((t + 1) * 64 + kvRow) * kHd + kvHalf * 32;
            const uint32_t dK = base + kvRow * G_ROWB + kvHalf * 64;
            const uint32_t dV = dK + A_TILE;
#pragma unroll
            for (int j = 0; j < 4; j++) cp16(dK + j * 16, ks + j * 8);
#pragma unroll
            for (int j = 0; j < 4; j++) cp16(dV + j * 16, vs + j * 8);
            cp_commit();
            cp_wait<1>();
        } else {
            cp_wait<0>();
        }
        __syncthreads();

        const uint32_t kB = sQ + A_KV + (t & 1) * 2 * A_TILE;
        const uint32_t vB = kB + A_TILE;

        // S = Q K^T
        float s[2][8][4];
#pragma unroll
        for (int mt = 0; mt < 2; mt++)
#pragma unroll
            for (int nt = 0; nt < 8; nt++)
#pragma unroll
                for (int i = 0; i < 4; i++) s[mt][nt][i] = 0.f;

#pragma unroll
        for (int ks = 0; ks < 4; ks++) {
            unsigned bf[8][2];
#pragma unroll
            for (int np = 0; np < 4; np++) {
                unsigned r0, r1, r2, r3;
                ldm_x4(r0, r1, r2, r3, kB + np * 16 * G_ROWB + ks * 32 + lOff);
                bf[2 * np][0] = r0; bf[2 * np + 1][0] = r1;
                bf[2 * np][1] = r2; bf[2 * np + 1][1] = r3;
            }
#pragma unroll
            for (int mt = 0; mt < 2; mt++)
#pragma unroll
                for (int nt = 0; nt < 8; nt++)
                    mma_fp16(s[mt][nt], qf[ks][mt], bf[nt]);
        }

        // Online softmax
#pragma unroll
        for (int mt = 0; mt < 2; mt++) {
            float t0 = -1e30f, t1 = -1e30f;
#pragma unroll
            for (int nt = 0; nt < 8; nt++) {
                t0 = fmaxf(t0, fmaxf(s[mt][nt][0], s[mt][nt][1]));
                t1 = fmaxf(t1, fmaxf(s[mt][nt][2], s[mt][nt][3]));
            }
            t0 = qredmax(t0);
            t1 = qredmax(t1);
            const float mn0 = fmaxf(mrun[mt][0], t0);
            const float mn1 = fmaxf(mrun[mt][1], t1);
            const float a0 = __expf(mrun[mt][0] - mn0);
            const float a1 = __expf(mrun[mt][1] - mn1);
            float s0 = 0.f, s1 = 0.f;
#pragma unroll
            for (int nt = 0; nt < 8; nt++) {
                s[mt][nt][0] = __expf(s[mt][nt][0] - mn0); s0 += s[mt][nt][0];
                s[mt][nt][1] = __expf(s[mt][nt][1] - mn0); s0 += s[mt][nt][1];
                s[mt][nt][2] = __expf(s[mt][nt][2] - mn1); s1 += s[mt][nt][2];
                s[mt][nt][3] = __expf(s[mt][nt][3] - mn1); s1 += s[mt][nt][3];
            }
            lrun[mt][0] = lrun[mt][0] * a0 + qredsum(s0);
            lrun[mt][1] = lrun[mt][1] * a1 + qredsum(s1);
            mrun[mt][0] = mn0;
            mrun[mt][1] = mn1;
#pragma unroll
            for (int nt = 0; nt < 8; nt++) {
                o[mt][nt][0] *= a0; o[mt][nt][1] *= a0;
                o[mt][nt][2] *= a1; o[mt][nt][3] *= a1;
            }
        }

        // O += P V (register-resident P; V frags via ldmatrix.trans)
#pragma unroll
        for (int ks = 0; ks < 4; ks++) {
            unsigned pf[2][4];
#pragma unroll
            for (int mt = 0; mt < 2; mt++) {
                pf[mt][0] = h2u(s[mt][2 * ks    ][0], s[mt][2 * ks    ][1]);
                pf[mt][1] = h2u(s[mt][2 * ks    ][2], s[mt][2 * ks    ][3]);
                pf[mt][2] = h2u(s[mt][2 * ks + 1][0], s[mt][2 * ks + 1][1]);
                pf[mt][3] = h2u(s[mt][2 * ks + 1][2], s[mt][2 * ks + 1][3]);
            }
            unsigned vf[8][2];
#pragma unroll
            for (int np = 0; np < 4; np++) {
                unsigned r0, r1, r2, r3;
                ldm_x4_t(r0, r1, r2, r3,
                         vB + ks * 16 * G_ROWB + np * 32 + lOff);
                vf[2 * np][0] = r0; vf[2 * np][1] = r1;
                vf[2 * np + 1][0] = r2; vf[2 * np + 1][1] = r3;
            }
#pragma unroll
            for (int mt = 0; mt < 2; mt++)
#pragma unroll
                for (int nt = 0; nt < 8; nt++)
                    mma_fp16(o[mt][nt], pf[mt], vf[nt]);
        }
        __syncthreads();
    }

    // Epilogue: normalize, write att (half) as [b, n, h*64+d]
#pragma unroll
    for (int mt = 0; mt < 2; mt++) {
        const float inv0 = 1.f / lrun[mt][0], inv1 = 1.f / lrun[mt][1];
        const int r0 = q0 + wq + mt * 16 + tg;
        const int r1 = r0 + 8;
#pragma unroll
        for (int nt = 0; nt < 8; nt++) {
            const int dd = nt * 8 + 2 * tl;
            *(__half2*)&g_att[(size_t)(bb * kSeq + r0) * kDim + hh * kHd + dd] =
                __floats2half2_rn(o[mt][nt][0] * inv0, o[mt][nt][1] * inv0);
            *(__half2*)&g_att[(size_t)(bb * kSeq + r1) * kDim + hh * kHd + dd] =
                __floats2half2_rn(o[mt][nt][2] * inv1, o[mt][nt][3] * inv1);
        }
    }
}

// ---------------------------------------------------------------------------
extern "C" void kernel_launch(void* const* d_in, const int* in_sizes, int n_in,
                              void* d_out, int out_size) {
    (void)in_sizes; (void)n_in; (void)out_size;
    const float* x      = (const float*)d_in[0];
    const float* w_qkv  = (const float*)d_in[1];
    const float* w_proj = (const float*)d_in[2];
    const float* b_proj = (const float*)d_in[3];
    float* out = (float*)d_out;

    cudaFuncSetAttribute(gemm5<0>, cudaFuncAttributeMaxDynamicSharedMemorySize, SMEM_G);
    cudaFuncSetAttribute(gemm5<1>, cudaFuncAttributeMaxDynamicSharedMemorySize, SMEM_G);
    cudaFuncSetAttribute(attn2, cudaFuncAttributeMaxDynamicSharedMemorySize, SMEM_A);

    // 0) fp32 -> fp16
    cvt_kernel<<<(kBatch * kSeq * kDim / 4 + 255) / 256, 256>>>(x, 0,
        kBatch * kSeq * kDim / 4);
    cvt_kernel<<<(3 * kDim * kDim / 4 + 255) / 256, 256>>>(w_qkv, 1,
        3 * kDim * kDim / 4);
    cvt_kernel<<<(kDim * kDim / 4 + 255) / 256, 256>>>(w_proj, 2,
        kDim * kDim / 4);

    // 1) QKV projection: M=8192, N=3072 -> g_q (x0.125) / g_k / g_v
    gemm5<0><<<dim3(3 * kDim / 128, kBatch * kSeq / 128), 256, SMEM_G>>>(
        nullptr, nullptr);

    // 2) Flash attention: 8 q-tiles x 128 heads
    attn2<<<kBatch * kHeads * (kSeq / 128), 128, SMEM_A>>>();

    // 3) Output projection + bias: M=8192, N=1024 -> f32 out
    gemm5<1><<<dim3(kDim / 128, kBatch * kSeq / 128), 256, SMEM_G>>>(
        b_proj, out);
}

// round 17
// speedup vs baseline: 1.0002x; 1.0002x over previous
#include <cuda_runtime.h>
#include <cuda_fp16.h>
#include <cstdint>

// ---------------------------------------------------------------------------
// x[8,1024,1024] -> qkv proj -> 16-head attention -> out proj (+bias)
// Legacy mma.sync m16n8k16 fp16/fp32. GEMMs: CTA 128x128, 256 threads,
// 8 warps (4Mx2N, warp tile 32x64), 3-stage cp.async, 2 CTAs per SM
// (round-15 evidence: single fat CTA serializes on its own barriers).
// ---------------------------------------------------------------------------

constexpr int kDim   = 1024;
constexpr int kBatch = 8;
constexpr int kSeq   = 1024;
constexpr int kHeads = 16;
constexpr int kHd    = 64;

// fp16 scratch (allocation-free rule: __device__ globals)
__device__ __half g_xh    [kBatch * kSeq * kDim];
__device__ __half g_wqkvh [3 * kDim * kDim];
__device__ __half g_wprojh[kDim * kDim];
__device__ __half g_q[kBatch * kHeads * kSeq * kHd];   // pre-scaled by 0.125
__device__ __half g_k[kBatch * kHeads * kSeq * kHd];
__device__ __half g_v[kBatch * kHeads * kSeq * kHd];
__device__ __half g_att[kBatch * kSeq * kDim];

// ------------------------------ helpers ------------------------------------
__device__ __forceinline__ uint32_t smem_u32(const void* p) {
    uint32_t a;
    asm("{ .reg .u64 t; cvta.to.shared.u64 t, %1; cvt.u32.u64 %0, t; }"
        : "=r"(a) : "l"(p));
    return a;
}
__device__ __forceinline__ void mma_fp16(float* c, const unsigned* a, const unsigned* b) {
    asm volatile(
        "mma.sync.aligned.m16n8k16.row.col.f32.f16.f16.f32 "
        "{%0,%1,%2,%3}, {%4,%5,%6,%7}, {%8,%9}, {%0,%1,%2,%3};"
        : "+f"(c[0]), "+f"(c[1]), "+f"(c[2]), "+f"(c[3])
        : "r"(a[0]), "r"(a[1]), "r"(a[2]), "r"(a[3]), "r"(b[0]), "r"(b[1]));
}
__device__ __forceinline__ void ldm_x4(unsigned& r0, unsigned& r1, unsigned& r2,
                                       unsigned& r3, uint32_t addr) {
    asm volatile("ldmatrix.sync.aligned.m8n8.x4.shared.b16 {%0,%1,%2,%3}, [%4];"
                 : "=r"(r0), "=r"(r1), "=r"(r2), "=r"(r3) : "r"(addr));
}
__device__ __forceinline__ void ldm_x4_t(unsigned& r0, unsigned& r1, unsigned& r2,
                                         unsigned& r3, uint32_t addr) {
    asm volatile("ldmatrix.sync.aligned.m8n8.x4.trans.shared.b16 {%0,%1,%2,%3}, [%4];"
                 : "=r"(r0), "=r"(r1), "=r"(r2), "=r"(r3) : "r"(addr));
}
__device__ __forceinline__ void cp16(uint32_t dst, const void* src) {
    asm volatile("cp.async.cg.shared.global [%0], [%1], 16;" :: "r"(dst), "l"(src));
}
__device__ __forceinline__ void cp_commit() {
    asm volatile("cp.async.commit_group;" ::: "memory");
}
template <int N>
__device__ __forceinline__ void cp_wait() {
    asm volatile("cp.async.wait_group %0;" :: "n"(N) : "memory");
}
__device__ __forceinline__ unsigned h2u(float a, float b) {
    __half2 h = __floats2half2_rn(a, b);
    return *reinterpret_cast<unsigned*>(&h);
}
__device__ __forceinline__ float qredmax(float v) {
    v = fmaxf(v, __shfl_xor_sync(0xffffffffu, v, 1));
    v = fmaxf(v, __shfl_xor_sync(0xffffffffu, v, 2));
    return v;
}
__device__ __forceinline__ float qredsum(float v) {
    v += __shfl_xor_sync(0xffffffffu, v, 1);
    v += __shfl_xor_sync(0xffffffffu, v, 2);
    return v;
}

// ---------------------------------------------------------------------------
// fp32 -> fp16 conversion (which: 0=x, 1=w_qkv, 2=w_proj)
// ---------------------------------------------------------------------------
__global__ void cvt_kernel(const float* __restrict__ src, int which, int n4) {
    int i = blockIdx.x * blockDim.x + threadIdx.x;
    if (i >= n4) return;
    __half* dst = (which == 0) ? g_xh : (which == 1) ? g_wqkvh : g_wprojh;
    float4 v = ((const float4*)src)[i];
    uint2 u;
    u.x = h2u(v.x, v.y);
    u.y = h2u(v.z, v.w);
    ((uint2*)dst)[i] = u;
}

// ---------------------------------------------------------------------------
// GEMM: C[m, f] = sum_c A[m, c] * B[f, c]   (fp16 K-major both; mma row.col)
// CTA 128(M) x 128(N), 256 threads, 8 warps: wm=warp&3 (32-row group),
// wn=warp>>2 (64-col group). Warp tile 32x64. K-slab 64, 3-stage cp.async,
// 2 CTAs per SM (launch_bounds(256,2); smem 110592 x 2 = 221KB <= 228KB).
// Rows padded to 144B: ldmatrix 8-row phases hit 32 distinct banks.
// MODE 0: A=g_xh, B=g_wqkvh; scatter half to g_q (x0.125)/g_k/g_v
// MODE 1: A=g_att, B=g_wprojh; add bias, f32 out
// ---------------------------------------------------------------------------
constexpr uint32_t G_ROWB = 144;
constexpr uint32_t A_ST   = 128 * G_ROWB;            // 18432
constexpr uint32_t B_ST   = 128 * G_ROWB;            // 18432
constexpr uint32_t G_ST   = A_ST + B_ST;             // 36864 per stage
constexpr uint32_t SMEM_G = 3 * G_ST;                // 110592
constexpr int kSlabs = kDim / 64;                    // 16

template <int MODE>
__global__ __launch_bounds__(256, 2)
void gemm5(const float* __restrict__ bias, float* __restrict__ C) {
    extern __shared__ char sm[];
    const uint32_t sb = smem_u32(sm);
    const int tid = threadIdx.x, warp = tid >> 5, lane = tid & 31;
    const int wm = warp & 3, wn = warp >> 2;         // 4(M) x 2(N) warps
    const int tg = lane >> 2, tl = lane & 3;
    const int m0 = blockIdx.y * 128, n0 = blockIdx.x * 128;

    const __half* Ag = (MODE == 0) ? g_xh : g_att;
    const __half* Bg = (MODE == 0) ? g_wqkvh : g_wprojh;

    // Loaders: 128 rows each, 2 thr/row, 4 cp16 (64B half-row) per thread.
    const int lR = tid >> 1, lH = tid & 1;
    const __half* aG = Ag + (size_t)(m0 + lR) * kDim + lH * 32;
    const __half* bG = Bg + (size_t)(n0 + lR) * kDim + lH * 32;
    const uint32_t aD = sb + lR * G_ROWB + lH * 64;
    const uint32_t bD = sb + A_ST + lR * G_ROWB + lH * 64;

    float acc[2][8][4];
#pragma unroll
    for (int mt = 0; mt < 2; mt++)
#pragma unroll
        for (int nt = 0; nt < 8; nt++)
#pragma unroll
            for (int i = 0; i < 4; i++) acc[mt][nt][i] = 0.f;

    const uint32_t lOff = (lane & 15) * G_ROWB + (lane >> 4) * 16;

    // prologue: slabs 0 and 1
#pragma unroll
    for (int p = 0; p < 2; p++) {
        const uint32_t off = p * G_ST;
        const int k0 = p * 64;
#pragma unroll
        for (int c = 0; c < 4; c++) cp16(aD + off + c * 16, aG + k0 + c * 8);
#pragma unroll
        for (int c = 0; c < 4; c++) cp16(bD + off + c * 16, bG + k0 + c * 8);
        cp_commit();
    }

    for (int s = 0; s < kSlabs; s++) {
        if (s + 2 < kSlabs) {
            const uint32_t off = ((s + 2) % 3) * G_ST;
            const int k0 = (s + 2) * 64;
#pragma unroll
            for (int c = 0; c < 4; c++) cp16(aD + off + c * 16, aG + k0 + c * 8);
#pragma unroll
            for (int c = 0; c < 4; c++) cp16(bD + off + c * 16, bG + k0 + c * 8);
            cp_commit();
            cp_wait<2>();
        } else if (s + 1 < kSlabs) {
            cp_wait<1>();
        } else {
            cp_wait<0>();
        }
        __syncthreads();   // stage s ready, prior consumers done

        const uint32_t st = sb + (s % 3) * G_ST;
        const uint32_t aS = st + wm * 32 * G_ROWB + lOff;
        const uint32_t bS = st + A_ST + wn * 64 * G_ROWB + lOff;
#pragma unroll
        for (int ks = 0; ks < 4; ks++) {
            unsigned af[2][4], bf[8][2];
#pragma unroll
            for (int mt = 0; mt < 2; mt++)
                ldm_x4(af[mt][0], af[mt][1], af[mt][2], af[mt][3],
                       aS + mt * 16 * G_ROWB + ks * 32);
#pragma unroll
            for (int np = 0; np < 4; np++) {
                unsigned r0, r1, r2, r3;
                ldm_x4(r0, r1, r2, r3, bS + np * 16 * G_ROWB + ks * 32);
                bf[2 * np][0] = r0; bf[2 * np + 1][0] = r1;
                bf[2 * np][1] = r2; bf[2 * np + 1][1] = r3;
            }
#pragma unroll
            for (int mt = 0; mt < 2; mt++)
#pragma unroll
                for (int nt = 0; nt < 8; nt++)
                    mma_fp16(acc[mt][nt], af[mt], bf[nt]);
        }
        __syncthreads();   // all warps done with stage s before it is refilled
    }

    // Epilogue
#pragma unroll
    for (int mt = 0; mt < 2; mt++) {
        const int mLo = m0 + wm * 32 + mt * 16 + tg;
        const int mHi = mLo + 8;
#pragma unroll
        for (int nt = 0; nt < 8; nt++) {
            const int f = n0 + wn * 64 + nt * 8 + 2 * tl;
            if (MODE == 0) {
                const int which = f >> 10;
                const int hh    = (f >> 6) & 15;
                const int dd    = f & 63;
                const float sc  = (which == 0) ? 0.125f : 1.f;   // fold q scale
                __half* dst = (which == 0) ? g_q : ((which == 1) ? g_k : g_v);
                {
                    int bb = mLo >> 10, nn = mLo & 1023;
                    size_t idx = ((size_t)(bb * kHeads + hh) * kSeq + nn) * kHd + dd;
                    *(__half2*)(dst + idx) =
                        __floats2half2_rn(acc[mt][nt][0] * sc, acc[mt][nt][1] * sc);
                }
                {
                    int bb = mHi >> 10, nn = mHi & 1023;
                    size_t idx = ((size_t)(bb * kHeads + hh) * kSeq + nn) * kHd + dd;
                    *(__half2*)(dst + idx) =
                        __floats2half2_rn(acc[mt][nt][2] * sc, acc[mt][nt][3] * sc);
                }
            } else {
                const float b0v = bias[f], b1v = bias[f + 1];
                *(float2*)(C + (size_t)mLo * kDim + f) =
                    make_float2(acc[mt][nt][0] + b0v, acc[mt][nt][1] + b1v);
                *(float2*)(C + (size_t)mHi * kDim + f) =
                    make_float2(acc[mt][nt][2] + b0v, acc[mt][nt][3] + b1v);
            }
        }
    }
}

// ---------------------------------------------------------------------------
// Flash attention: CTA = 128 q-rows of one (b,h); 4 warps x 32 rows.
// KV tiles 64, cp.async double-buffered. K frags via ldmatrix; V frags via
// ldmatrix.trans on natural [kv][d] layout; P kept in registers. Q pre-scaled.
// ---------------------------------------------------------------------------
constexpr uint32_t A_KV   = 128 * G_ROWB;            // Q region size: 18432
constexpr uint32_t A_TILE = 64 * G_ROWB;             // 9216
constexpr uint32_t SMEM_A = A_KV + 2 * 2 * A_TILE;   // 55296

__global__ __launch_bounds__(128)
void attn2() {
    extern __shared__ char sm[];
    const uint32_t sQ = smem_u32(sm);
    const int bx = blockIdx.x;
    const int qt = bx & 7;
    const int bh = bx >> 3;
    const int bb = bh >> 4;
    const int hh = bh & 15;
    const int tid = threadIdx.x, warp = tid >> 5, lane = tid & 31;
    const int tg = lane >> 2, tl = lane & 3;
    const int q0 = qt * 128;
    const int wq = warp * 32;

    const __half* Qp = g_q + (size_t)(bb * kHeads + hh) * kSeq * kHd;
    const __half* Kp = g_k + (size_t)(bb * kHeads + hh) * kSeq * kHd;
    const __half* Vp = g_v + (size_t)(bb * kHeads + hh) * kSeq * kHd;

    const int kvRow = tid >> 1, kvHalf = tid & 1;

    // prologue: KV tile 0
    {
        const __half* ks = Kp + (size_t)kvRow * kHd + kvHalf * 32;
        const __half* vs = Vp + (size_t)kvRow * kHd + kvHalf * 32;
        const uint32_t dK = sQ + A_KV + kvRow * G_ROWB + kvHalf * 64;
        const uint32_t dV = dK + A_TILE;
#pragma unroll
        for (int j = 0; j < 4; j++) cp16(dK + j * 16, ks + j * 8);
#pragma unroll
        for (int j = 0; j < 4; j++) cp16(dV + j * 16, vs + j * 8);
        cp_commit();
    }

    // Stage Q (pre-scaled by 0.125 at QKV epilogue)
    {
        const __half* qr = Qp + (size_t)(q0 + tid) * kHd;
        char* qd = sm + tid * G_ROWB;
#pragma unroll
        for (int j = 0; j < 8; j++)
            *(uint4*)(qd + j * 16) = *(const uint4*)(qr + j * 8);
    }
    __syncthreads();

    const uint32_t lOff = (lane & 15) * G_ROWB + (lane >> 4) * 16;
    unsigned qf[4][2][4];
    {
        const uint32_t qBase = sQ + wq * G_ROWB + lOff;
#pragma unroll
        for (int ks = 0; ks < 4; ks++)
#pragma unroll
            for (int mt = 0; mt < 2; mt++)
                ldm_x4(qf[ks][mt][0], qf[ks][mt][1], qf[ks][mt][2], qf[ks][mt][3],
                       qBase + mt * 16 * G_ROWB + ks * 32);
    }

    float o[2][8][4];
#pragma unroll
    for (int mt = 0; mt < 2; mt++)
#pragma unroll
        for (int nt = 0; nt < 8; nt++)
#pragma unroll
            for (int i = 0; i < 4; i++) o[mt][nt][i] = 0.f;
    float mrun[2][2] = {{-1e30f, -1e30f}, {-1e30f, -1e30f}};
    float lrun[2][2] = {{0.f, 0.f}, {0.f, 0.f}};

    for (int t = 0; t < 16; t++) {
        if (t + 1 < 16) {
            const uint32_t base = sQ + A_KV + ((t + 1) & 1) * 2 * A_TILE;
            const __half* ks = Kp + (size_t)((t + 1) * 64 + kvRow) * kHd + kvHalf * 32;
            const __half* vs = Vp + (size_t)((t + 1) * 64 + kvRow) * kHd + kvHalf * 32;
            const uint32_t dK = base + kvRow * G_ROWB + kvHalf * 64;
            const uint32_t dV = dK + A_TILE;
#pragma unroll
            for (int j = 0; j < 4; j++) cp16(dK + j * 16, ks + j * 8);
#pragma unroll
            for (int j = 0; j < 4; j++) cp16(dV + j * 16, vs + j * 8);
            cp_commit();
            cp_wait<1>();
        } else {
            cp_wait<0>();
        }
        __syncthreads();

        const uint32_t kB = sQ + A_KV + (t & 1) * 2 * A_TILE;
        const uint32_t vB = kB + A_TILE;

        // S = Q K^T
        float s[2][8][4];
#pragma unroll
        for (int mt = 0; mt < 2; mt++)
#pragma unroll
            for (int nt = 0; nt < 8; nt++)
#pragma unroll
                for (int i = 0; i < 4; i++) s[mt][nt][i] = 0.f;

#pragma unroll
        for (int ks = 0; ks < 4; ks++) {
            unsigned bf[8][2];
#pragma unroll
            for (int np = 0; np < 4; np++) {
                unsigned r0, r1, r2, r3;
                ldm_x4(r0, r1, r2, r3, kB + np * 16 * G_ROWB + ks * 32 + lOff);
                bf[2 * np][0] = r0; bf[2 * np + 1][0] = r1;
                bf[2 * np][1] = r2; bf[2 * np + 1][1] = r3;
            }
#pragma unroll
            for (int mt = 0; mt < 2; mt++)
#pragma unroll
                for (int nt = 0; nt < 8; nt++)
                    mma_fp16(s[mt][nt], qf[ks][mt], bf[nt]);
        }

        // Online softmax
#pragma unroll
        for (int mt = 0; mt < 2; mt++) {
            float t0 = -1e30f, t1 = -1e30f;
#pragma unroll
            for (int nt = 0; nt < 8; nt++) {
                t0 = fmaxf(t0, fmaxf(s[mt][nt][0], s[mt][nt][1]));
                t1 = fmaxf(t1, fmaxf(s[mt][nt][2], s[mt][nt][3]));
            }
            t0 = qredmax(t0);
            t1 = qredmax(t1);
            const float mn0 = fmaxf(mrun[mt][0], t0);
            const float mn1 = fmaxf(mrun[mt][1], t1);
            const float a0 = __expf(mrun[mt][0] - mn0);
            const float a1 = __expf(mrun[mt][1] - mn1);
            float s0 = 0.f, s1 = 0.f;
#pragma unroll
            for (int nt = 0; nt < 8; nt++) {
                s[mt][nt][0] = __expf(s[mt][nt][0] - mn0); s0 += s[mt][nt][0];
                s[mt][nt][1] = __expf(s[mt][nt][1] - mn0); s0 += s[mt][nt][1];
                s[mt][nt][2] = __expf(s[mt][nt][2] - mn1); s1 += s[mt][nt][2];
                s[mt][nt][3] = __expf(s[mt][nt][3] - mn1); s1 += s[mt][nt][3];
            }
            lrun[mt][0] = lrun[mt][0] * a0 + qredsum(s0);
            lrun[mt][1] = lrun[mt][1] * a1 + qredsum(s1);
            mrun[mt][0] = mn0;
            mrun[mt][1] = mn1;
#pragma unroll
            for (int nt = 0; nt < 8; nt++) {
                o[mt][nt][0] *= a0; o[mt][nt][1] *= a0;
                o[mt][nt][2] *= a1; o[mt][nt][3] *= a1;
            }
        }

        // O += P V (register-resident P; V frags via ldmatrix.trans)
#pragma unroll
        for (int ks = 0; ks < 4; ks++) {
            unsigned pf[2][4];
#pragma unroll
            for (int mt = 0; mt < 2; mt++) {
                pf[mt][0] = h2u(s[mt][2 * ks    ][0], s[mt][2 * ks    ][1]);
                pf[mt][1] = h2u(s[mt][2 * ks    ][2], s[mt][2 * ks    ][3]);
                pf[mt][2] = h2u(s[mt][2 * ks + 1][0], s[mt][2 * ks + 1][1]);
                pf[mt][3] = h2u(s[mt][2 * ks + 1][2], s[mt][2 * ks + 1][3]);
            }
            unsigned vf[8][2];
#pragma unroll
            for (int np = 0; np < 4; np++) {
                unsigned r0, r1, r2, r3;
                ldm_x4_t(r0, r1, r2, r3,
                         vB + ks * 16 * G_ROWB + np * 32 + lOff);
                vf[2 * np][0] = r0; vf[2 * np][1] = r1;
                vf[2 * np + 1][0] = r2; vf[2 * np + 1][1] = r3;
            }
#pragma unroll
            for (int mt = 0; mt < 2; mt++)
#pragma unroll
                for (int nt = 0; nt < 8; nt++)
                    mma_fp16(o[mt][nt], pf[mt], vf[nt]);
        }
        __syncthreads();
    }

    // Epilogue: normalize, write att (half) as [b, n, h*64+d]
#pragma unroll
    for (int mt = 0; mt < 2; mt++) {
        const float inv0 = 1.f / lrun[mt][0], inv1 = 1.f / lrun[mt][1];
        const int r0 = q0 + wq + mt * 16 + tg;
        const int r1 = r0 + 8;
#pragma unroll
        for (int nt = 0; nt < 8; nt++) {
            const int dd = nt * 8 + 2 * tl;
            *(__half2*)&g_att[(size_t)(bb * kSeq + r0) * kDim + hh * kHd + dd] =
                __floats2half2_rn(o[mt][nt][0] * inv0, o[mt][nt][1] * inv0);
            *(__half2*)&g_att[(size_t)(bb * kSeq + r1) * kDim + hh * kHd + dd] =
                __floats2half2_rn(o[mt][nt][2] * inv1, o[mt][nt][3] * inv1);
        }
    }
}

// ---------------------------------------------------------------------------
extern "C" void kernel_launch(void* const* d_in, const int* in_sizes, int n_in,
                              void* d_out, int out_size) {
    (void)in_sizes; (void)n_in; (void)out_size;
    const float* x      = (const float*)d_in[0];
    const float* w_qkv  = (const float*)d_in[1];
    const float* w_proj = (const float*)d_in[2];
    const float* b_proj = (const float*)d_in[3];
    float* out = (float*)d_out;

    cudaFuncSetAttribute(gemm5<0>, cudaFuncAttributeMaxDynamicSharedMemorySize, SMEM_G);
    cudaFuncSetAttribute(gemm5<1>, cudaFuncAttributeMaxDynamicSharedMemorySize, SMEM_G);
    cudaFuncSetAttribute(attn2, cudaFuncAttributeMaxDynamicSharedMemorySize, SMEM_A);

    // 0) fp32 -> fp16
    cvt_kernel<<<(kBatch * kSeq * kDim / 4 + 255) / 256, 256>>>(x, 0,
        kBatch * kSeq * kDim / 4);
    cvt_kernel<<<(3 * kDim * kDim / 4 + 255) / 256, 256>>>(w_qkv, 1,
        3 * kDim * kDim / 4);
    cvt_kernel<<<(kDim * kDim / 4 + 255) / 256, 256>>>(w_proj, 2,
        kDim * kDim / 4);

    // 1) QKV projection: M=8192, N=3072 -> g_q (x0.125) / g_k / g_v
    gemm5<0><<<dim3(3 * kDim / 128, kBatch * kSeq / 128), 256, SMEM_G>>>(
        nullptr, nullptr);

    // 2) Flash attention: 8 q-tiles x 128 heads
    attn2<<<kBatch * kHeads * (kSeq / 128), 128, SMEM_A>>>();

    // 3) Output projection + bias: M=8192, N=1024 -> f32 out
    gemm5<1><<<dim3(kDim / 128, kBatch * kSeq / 128), 256, SMEM_G>>>(
        b_proj, out);
}